// round 2
// baseline (speedup 1.0000x reference)
#include <cuda_runtime.h>
#include <cuda_bf16.h>
#include <stdint.h>

#define NCLS 6
#define HDIM 512
#define WDIM 512
#define NB   8
#define NPIX (NB * HDIM * WDIM)   // 2097152
#define IMG  (HDIM * WDIM)        // 262144

// 2 MB scratch for horizontal 11-window sums (values <= 55 fit in uint8)
__device__ unsigned char g_hsum[NPIX];
// Global accumulators
__device__ double g_accA;  // sum over all pixels of lp_label
__device__ double g_accB;  // sum over edge pixels of lp_sum
__device__ double g_accC;  // sum over edge pixels of lp_label
__device__ unsigned long long g_accE;  // edge pixel count
__device__ unsigned int g_done;        // completed-block counter

// Kernel 1: one block per row (b*512 + h). hsum[w] = sum_{dw=-5..5} t[w+dw] (zero OOB).
// Block 0 / thread 0 also resets the accumulators (safe: kernel 2 runs after).
__global__ void ls_hsum_kernel(const int* __restrict__ target) {
    if (blockIdx.x == 0 && threadIdx.x == 0) {
        g_accA = 0.0; g_accB = 0.0; g_accC = 0.0;
        g_accE = 0ULL; g_done = 0u;
    }
    __shared__ int srow[WDIM];
    const int row = blockIdx.x;
    const int* trow = target + (size_t)row * WDIM;
    for (int i = threadIdx.x; i < WDIM; i += blockDim.x) srow[i] = trow[i];
    __syncthreads();
    for (int w = threadIdx.x; w < WDIM; w += blockDim.x) {
        int s = 0;
#pragma unroll
        for (int d = -5; d <= 5; d++) {
            int ww = w + d;
            if (ww >= 0 && ww < WDIM) s += srow[ww];
        }
        g_hsum[(size_t)row * WDIM + w] = (unsigned char)s;
    }
}

// Kernel 2: main. Each thread processes 4 consecutive-w pixels; the last block
// to finish performs the finalization and writes the scalar output.
__global__ void __launch_bounds__(256) ls_main_kernel(const float* __restrict__ x,
                                                      const int* __restrict__ target,
                                                      float* __restrict__ out) {
    const int tix = blockIdx.x * blockDim.x + threadIdx.x;  // 0 .. NPIX/4-1
    const int base = tix << 2;                               // pixel index, mult of 4
    const int b = base >> 18;                                // / 262144
    const int rem = base & (IMG - 1);                        // h*512 + w
    const int h = rem >> 9;

    // Vertical 11-tap sum of uint8 horizontal sums (zero-padded rows). L2-resident.
    int S0 = 0, S1 = 0, S2 = 0, S3 = 0;
#pragma unroll
    for (int d = -5; d <= 5; d++) {
        int hh = h + d;
        if (hh >= 0 && hh < HDIM) {
            uchar4 hv = *reinterpret_cast<const uchar4*>(&g_hsum[base + d * WDIM]);
            S0 += hv.x; S1 += hv.y; S2 += hv.z; S3 += hv.w;
        }
    }
    int S[4] = {S0, S1, S2, S3};

    const int4 lab4 = *reinterpret_cast<const int4*>(&target[base]);
    int lab[4] = {lab4.x, lab4.y, lab4.z, lab4.w};

    // Load 6 channels x 4 pixels as float4s, streaming (read-once data).
    const float* xb = x + (size_t)b * (NCLS * IMG) + rem;
    float v[NCLS][4];
#pragma unroll
    for (int c = 0; c < NCLS; c++) {
        float4 t = __ldcs(reinterpret_cast<const float4*>(&xb[(size_t)c * IMG]));
        v[c][0] = t.x; v[c][1] = t.y; v[c][2] = t.z; v[c][3] = t.w;
    }

    float tA = 0.f, tB = 0.f, tC = 0.f;
    int tE = 0;
#pragma unroll
    for (int j = 0; j < 4; j++) {
        float m = v[0][j];
#pragma unroll
        for (int c = 1; c < NCLS; c++) m = fmaxf(m, v[c][j]);
        float se = 0.f, sumx = 0.f, xl = 0.f;
#pragma unroll
        for (int c = 0; c < NCLS; c++) {
            float vc = v[c][j];
            se += __expf(vc - m);
            sumx += vc;
            xl = (lab[j] == c) ? vc : xl;  // predicated select, no dynamic index
        }
        float lse = __logf(se);
        float lpl = xl - m - lse;              // log_p at the label
        float lps = sumx - 6.0f * (m + lse);   // sum over classes of log_p

        tA += lpl;
        bool edge = (121 * lab[j] != S[j]);
        if (edge) { tE++; tB += lps; tC += lpl; }
    }

    // Warp reduction
#pragma unroll
    for (int off = 16; off > 0; off >>= 1) {
        tA += __shfl_down_sync(0xffffffffu, tA, off);
        tB += __shfl_down_sync(0xffffffffu, tB, off);
        tC += __shfl_down_sync(0xffffffffu, tC, off);
        tE += __shfl_down_sync(0xffffffffu, tE, off);
    }

    __shared__ float sA[8], sB[8], sC[8];
    __shared__ int sE[8];
    const int warp = threadIdx.x >> 5;
    const int lane = threadIdx.x & 31;
    if (lane == 0) { sA[warp] = tA; sB[warp] = tB; sC[warp] = tC; sE[warp] = tE; }
    __syncthreads();
    if (warp == 0) {
        float rA = (lane < 8) ? sA[lane] : 0.f;
        float rB = (lane < 8) ? sB[lane] : 0.f;
        float rC = (lane < 8) ? sC[lane] : 0.f;
        int   rE = (lane < 8) ? sE[lane] : 0;
#pragma unroll
        for (int off = 4; off > 0; off >>= 1) {
            rA += __shfl_down_sync(0xffffffffu, rA, off);
            rB += __shfl_down_sync(0xffffffffu, rB, off);
            rC += __shfl_down_sync(0xffffffffu, rC, off);
            rE += __shfl_down_sync(0xffffffffu, rE, off);
        }
        if (lane == 0) {
            atomicAdd(&g_accA, (double)rA);
            atomicAdd(&g_accB, (double)rB);
            atomicAdd(&g_accC, (double)rC);
            atomicAdd(&g_accE, (unsigned long long)rE);

            // Last-block finalization
            __threadfence();
            unsigned int ticket = atomicAdd(&g_done, 1u);
            if (ticket == gridDim.x - 1) {
                double A = atomicAdd(&g_accA, 0.0);
                double B = atomicAdd(&g_accB, 0.0);
                double C = atomicAdd(&g_accC, 0.0);
                unsigned long long E = atomicAdd(&g_accE, 0ULL);
                const double n = (double)NPIX;
                double s = (double)E / n;
                if (s > 0.2) s = 0.2;
                double total = A + s * (B - (11.0 / 6.0) * C);
                out[0] = (float)(-(total / n));
            }
        }
    }
}

extern "C" void kernel_launch(void* const* d_in, const int* in_sizes, int n_in,
                              void* d_out, int out_size) {
    const float* x = (const float*)d_in[0];
    const int* target = (const int*)d_in[1];
    float* out = (float*)d_out;

    ls_hsum_kernel<<<NB * HDIM, 128>>>(target);
    ls_main_kernel<<<NPIX / 4 / 256, 256>>>(x, target, out);
}

// round 3
// speedup vs baseline: 1.0818x; 1.0818x over previous
#include <cuda_runtime.h>
#include <cuda_bf16.h>
#include <stdint.h>

#define NCLS 6
#define HDIM 512
#define WDIM 512
#define NB   8
#define NPIX (NB * HDIM * WDIM)   // 2097152
#define IMG  (HDIM * WDIM)        // 262144

#define TILE 64
#define HALO 5
#define SRC  (TILE + 2 * HALO)    // 74

// Packed per-pixel byte: bits[2:0] = label, bit 3 = edge flag.
__device__ unsigned char g_le[NPIX];
// Global accumulators
__device__ double g_accA;  // sum over all pixels of lp_label
__device__ double g_accB;  // sum over edge pixels of lp_sum
__device__ double g_accC;  // sum over edge pixels of lp_label
__device__ unsigned long long g_accE;  // edge pixel count
__device__ unsigned int g_done;        // completed-block counter

// Kernel 1: per 64x64 tile, compute 11x11 window sum of target (zero pad) and
// emit packed label|edge byte. Sliding-window adds keep ALU cost ~5 adds/px.
__global__ void __launch_bounds__(256) ls_edge_kernel(const int* __restrict__ target) {
    if (blockIdx.x == 0 && threadIdx.x == 0) {
        g_accA = 0.0; g_accB = 0.0; g_accC = 0.0;
        g_accE = 0ULL; g_done = 0u;
    }

    __shared__ int sT[SRC][SRC + 1];   // 74 x 75 ints
    __shared__ int sH[SRC][TILE + 1];  // horizontal window sums, 74 x 65

    const int bx = blockIdx.x;          // 0 .. 511
    const int b  = bx >> 6;             // batch
    const int tile = bx & 63;
    const int y0 = (tile >> 3) * TILE;
    const int x0 = (tile & 7) * TILE;
    const int tid = threadIdx.x;
    const int* timg = target + (size_t)b * IMG;

    // Load 74x74 source (clamped to zero outside image).
    for (int idx = tid; idx < SRC * SRC; idx += 256) {
        const int r = idx / SRC, c = idx - r * SRC;
        const int gy = y0 + r - HALO, gx = x0 + c - HALO;
        int val = 0;
        if (gy >= 0 && gy < HDIM && gx >= 0 && gx < WDIM)
            val = timg[gy * WDIM + gx];
        sT[r][c] = val;
    }
    __syncthreads();

    // Horizontal 11-window sums: 74 rows x 4 segments of 16 outputs (sliding).
    for (int seg = tid; seg < SRC * 4; seg += 256) {
        const int r = seg >> 2;
        const int c0 = (seg & 3) * 16;
        int s = 0;
#pragma unroll
        for (int d = 0; d < 11; d++) s += sT[r][c0 + d];
        sH[r][c0] = s;
#pragma unroll
        for (int i = 1; i < 16; i++) {
            s += sT[r][c0 + i + 10] - sT[r][c0 + i - 1];
            sH[r][c0 + i] = s;
        }
    }
    __syncthreads();

    // Vertical 11-window sums: 256 threads, each owns (col, 16-row segment).
    {
        const int c = tid & 63;
        const int r0 = (tid >> 6) * 16;
        int S = 0;
#pragma unroll
        for (int d = 0; d < 11; d++) S += sH[r0 + d][c];
        unsigned char* orow = &g_le[(size_t)b * IMG + (y0 + r0) * WDIM + x0 + c];
#pragma unroll
        for (int i = 0; i < 16; i++) {
            if (i > 0) S += sH[r0 + i + 10][c] - sH[r0 + i - 1][c];
            const int lab = sT[r0 + i + HALO][c + HALO];
            const int edge = (121 * lab != S) ? 8 : 0;
            orow[i * WDIM] = (unsigned char)(lab | edge);
        }
    }
}

// Kernel 2: main. Each thread processes 4 consecutive-w pixels; the last block
// to finish performs the finalization and writes the scalar output.
__global__ void __launch_bounds__(256) ls_main_kernel(const float* __restrict__ x,
                                                      float* __restrict__ out) {
    const int tix = blockIdx.x * blockDim.x + threadIdx.x;  // 0 .. NPIX/4-1
    const int base = tix << 2;                               // pixel index, mult of 4
    const int b = base >> 18;                                // / 262144
    const int rem = base & (IMG - 1);                        // h*512 + w

    // Packed label|edge bytes (written by kernel 1, L2-resident).
    const uchar4 le4 = *reinterpret_cast<const uchar4*>(&g_le[base]);
    const int le[4] = {le4.x, le4.y, le4.z, le4.w};

    // Load 6 channels x 4 pixels as float4s, streaming (read-once data).
    const float* xb = x + (size_t)b * (NCLS * IMG) + rem;
    float v[NCLS][4];
#pragma unroll
    for (int c = 0; c < NCLS; c++) {
        float4 t = __ldcs(reinterpret_cast<const float4*>(&xb[(size_t)c * IMG]));
        v[c][0] = t.x; v[c][1] = t.y; v[c][2] = t.z; v[c][3] = t.w;
    }

    float tA = 0.f, tB = 0.f, tC = 0.f;
    int tE = 0;
#pragma unroll
    for (int j = 0; j < 4; j++) {
        const int lab = le[j] & 7;
        float m = v[0][j];
#pragma unroll
        for (int c = 1; c < NCLS; c++) m = fmaxf(m, v[c][j]);
        float se = 0.f, sumx = 0.f, xl = 0.f;
#pragma unroll
        for (int c = 0; c < NCLS; c++) {
            float vc = v[c][j];
            se += __expf(vc - m);
            sumx += vc;
            xl = (lab == c) ? vc : xl;  // predicated select, no dynamic index
        }
        float lse = __logf(se);
        float lpl = xl - m - lse;              // log_p at the label
        float lps = sumx - 6.0f * (m + lse);   // sum over classes of log_p

        tA += lpl;
        if (le[j] & 8) { tE++; tB += lps; tC += lpl; }
    }

    // Warp reduction
#pragma unroll
    for (int off = 16; off > 0; off >>= 1) {
        tA += __shfl_down_sync(0xffffffffu, tA, off);
        tB += __shfl_down_sync(0xffffffffu, tB, off);
        tC += __shfl_down_sync(0xffffffffu, tC, off);
        tE += __shfl_down_sync(0xffffffffu, tE, off);
    }

    __shared__ float sA[8], sB[8], sC[8];
    __shared__ int sE[8];
    const int warp = threadIdx.x >> 5;
    const int lane = threadIdx.x & 31;
    if (lane == 0) { sA[warp] = tA; sB[warp] = tB; sC[warp] = tC; sE[warp] = tE; }
    __syncthreads();
    if (warp == 0) {
        float rA = (lane < 8) ? sA[lane] : 0.f;
        float rB = (lane < 8) ? sB[lane] : 0.f;
        float rC = (lane < 8) ? sC[lane] : 0.f;
        int   rE = (lane < 8) ? sE[lane] : 0;
#pragma unroll
        for (int off = 4; off > 0; off >>= 1) {
            rA += __shfl_down_sync(0xffffffffu, rA, off);
            rB += __shfl_down_sync(0xffffffffu, rB, off);
            rC += __shfl_down_sync(0xffffffffu, rC, off);
            rE += __shfl_down_sync(0xffffffffu, rE, off);
        }
        if (lane == 0) {
            atomicAdd(&g_accA, (double)rA);
            atomicAdd(&g_accB, (double)rB);
            atomicAdd(&g_accC, (double)rC);
            atomicAdd(&g_accE, (unsigned long long)rE);

            // Last-block finalization
            __threadfence();
            unsigned int ticket = atomicAdd(&g_done, 1u);
            if (ticket == gridDim.x - 1) {
                double A = atomicAdd(&g_accA, 0.0);
                double B = atomicAdd(&g_accB, 0.0);
                double C = atomicAdd(&g_accC, 0.0);
                unsigned long long E = atomicAdd(&g_accE, 0ULL);
                const double n = (double)NPIX;
                double s = (double)E / n;
                if (s > 0.2) s = 0.2;
                double total = A + s * (B - (11.0 / 6.0) * C);
                out[0] = (float)(-(total / n));
            }
        }
    }
}

extern "C" void kernel_launch(void* const* d_in, const int* in_sizes, int n_in,
                              void* d_out, int out_size) {
    const float* x = (const float*)d_in[0];
    const int* target = (const int*)d_in[1];
    float* out = (float*)d_out;

    ls_edge_kernel<<<NB * 64, 256>>>(target);
    ls_main_kernel<<<NPIX / 4 / 256, 256>>>(x, out);
}